// round 1
// baseline (speedup 1.0000x reference)
#include <cuda_runtime.h>
#include <cuda_bf16.h>
#include <cstdint>

#define BATCH 128
#define NN    512
#define KNB   16
#define BN    (BATCH*NN)
#define NEGS  0.01f

// ---------------- scratch (device globals; no allocation allowed) -------------
__device__ float g_xx[BN*5];
__device__ float g_x1[BN*64];
__device__ float g_x2[BN*64];
__device__ int   g_idx[BN*KNB];
__device__ float g_A[(size_t)BN*128];
__device__ float g_C[(size_t)BN*128];
__device__ float g_pool[BATCH*256];

__device__ __forceinline__ float leaky(float v){ return v > 0.f ? v : NEGS*v; }

__device__ __forceinline__ void atomicMaxFloat(float* addr, float value){
    if (value >= 0.f) atomicMax((int*)addr, __float_as_int(value));
    else              atomicMin((unsigned int*)addr, __float_as_uint(value));
}

// ---------------- 0) build xx = [tq, x, pos] ---------------------------------
__global__ void k_build(const float* __restrict__ x, const float* __restrict__ pos,
                        const float* __restrict__ tq){
    int i = blockIdx.x*blockDim.x + threadIdx.x;
    if (i < BN){
        g_xx[i*5+0] = tq[i];
        g_xx[i*5+1] = x[i];
        g_xx[i*5+2] = pos[i*3+0];
        g_xx[i*5+3] = pos[i*3+1];
        g_xx[i*5+4] = pos[i*3+2];
    }
}

__global__ void k_initpool(){
    int i = blockIdx.x*blockDim.x + threadIdx.x;
    if (i < BATCH*256) g_pool[i] = __int_as_float(0xff800000); // -inf
}

// ---------------- 1) kNN: warp per query, smem-tiled -------------------------
// d2 = sq_i + sq_j - 2*dot  (matches reference formula); pick 16 smallest with
// lower-index tiebreak (JAX top_k stability).
template<int D>
__global__ void k_knn(){
    const int TILE = 128;
    const int PAD  = D + 1;
    __shared__ float tile[TILE*PAD];
    __shared__ float sqs[TILE];
    __shared__ float fi[8][D];
    __shared__ float fsq[8];

    int b  = blockIdx.x >> 6;            // NN/8 = 64 blocks per graph
    int q0 = (blockIdx.x & 63) * 8;
    int warp = threadIdx.x >> 5, lane = threadIdx.x & 31;
    int qi = q0 + warp;

    const float* F = (D == 5) ? g_xx : g_x1;
    const float* Fb = F + (size_t)b*NN*D;

    for (int d = lane; d < D; d += 32) fi[warp][d] = Fb[qi*D + d];
    __syncwarp();
    if (lane == 0){
        float s = 0.f;
        #pragma unroll
        for (int d = 0; d < D; d++) s += fi[warp][d]*fi[warp][d];
        fsq[warp] = s;
    }
    __syncwarp();
    float sqi = fsq[warp];

    float d2loc[16];
    for (int t = 0; t < NN/TILE; t++){
        __syncthreads();
        for (int idx = threadIdx.x; idx < TILE*D; idx += 256){
            int r = idx / D, c = idx % D;
            tile[r*PAD + c] = Fb[(t*TILE + r)*D + c];
        }
        __syncthreads();
        if (threadIdx.x < TILE){
            float s = 0.f;
            #pragma unroll
            for (int d = 0; d < D; d++){
                float v = tile[threadIdx.x*PAD + d];
                s += v*v;
            }
            sqs[threadIdx.x] = s;
        }
        __syncthreads();
        #pragma unroll
        for (int u = 0; u < TILE/32; u++){
            int jj = u*32 + lane;
            float dot = 0.f;
            #pragma unroll
            for (int d = 0; d < D; d++) dot += fi[warp][d]*tile[jj*PAD + d];
            d2loc[t*(TILE/32) + u] = sqi + sqs[jj] - 2.f*dot;
        }
    }

    int* myidx = g_idx + ((size_t)b*NN + qi)*KNB;
    for (int r = 0; r < KNB; r++){
        float bv = 3.0e38f; int bj = 0x7fffffff;
        #pragma unroll
        for (int u = 0; u < 16; u++){
            int j = u*32 + lane;
            float v = d2loc[u];
            if (v < bv || (v == bv && j < bj)){ bv = v; bj = j; }
        }
        #pragma unroll
        for (int off = 16; off > 0; off >>= 1){
            float ov = __shfl_xor_sync(0xffffffffu, bv, off);
            int   oj = __shfl_xor_sync(0xffffffffu, bj, off);
            if (ov < bv || (ov == bv && oj < bj)){ bv = ov; bj = oj; }
        }
        if (lane == 0) myidx[r] = bj;
        if (lane == (bj & 31)){
            #pragma unroll
            for (int u = 0; u < 16; u++) if (u == (bj >> 5)) d2loc[u] = 3.4e38f;
        }
    }
}

// ---------------- 2) edge-layer-1 factorization ------------------------------
// A[i] = xi @ (W_top - W_bot) + b ;  C[j] = xj @ W_bot
template<int DIN, int H>
__global__ void k_convA(const float* __restrict__ W, const float* __restrict__ bias){
    int t = blockIdx.x*blockDim.x + threadIdx.x;
    if (t >= BN*H) return;
    int i = t / H, c = t % H;
    const float* F = (DIN == 5) ? g_xx : g_x1;
    const float* f = F + (size_t)i*DIN;
    float a = bias[c], cc = 0.f;
    #pragma unroll
    for (int d = 0; d < DIN; d++){
        float v  = f[d];
        float wt = W[d*H + c];
        float wb = W[(DIN + d)*H + c];
        a  += v*(wt - wb);
        cc += v*wb;
    }
    g_A[(size_t)i*H + c] = a;
    g_C[(size_t)i*H + c] = cc;
}

// ---------------- 3) edge MLP second layer + max over K ----------------------
// per edge: h = leaky(A[i] + C[j]) ; out = leaky(h @ Wb + bb) ; max over K
template<int H>
__global__ void k_edge(const float* __restrict__ W, const float* __restrict__ bias){
    __shared__ float Ws[H*64];
    __shared__ float bs[64];
    __shared__ float hs[8][H];
    for (int i = threadIdx.x; i < H*64; i += 256) Ws[i] = W[i];
    if (threadIdx.x < 64) bs[threadIdx.x] = bias[threadIdx.x];
    __syncthreads();

    int warp = threadIdx.x >> 5, lane = threadIdx.x & 31;
    int node = blockIdx.x*8 + warp;
    int b = node / NN;
    float* out = (H == 64) ? g_x1 : g_x2;

    const float* Arow = g_A + (size_t)node*H;
    float a[H/32];
    #pragma unroll
    for (int u = 0; u < H/32; u++) a[u] = Arow[lane + 32*u];

    float m0 = -3.4e38f, m1 = -3.4e38f;
    const int* nb = g_idx + (size_t)node*KNB;
    for (int k = 0; k < KNB; k++){
        int j = b*NN + nb[k];
        const float* Crow = g_C + (size_t)j*H;
        __syncwarp();
        #pragma unroll
        for (int u = 0; u < H/32; u++)
            hs[warp][lane + 32*u] = leaky(a[u] + Crow[lane + 32*u]);
        __syncwarp();
        float acc0 = 0.f, acc1 = 0.f;
        #pragma unroll 8
        for (int kk = 0; kk < H; kk++){
            float hv = hs[warp][kk];
            acc0 += hv * Ws[kk*64 + lane];
            acc1 += hv * Ws[kk*64 + lane + 32];
        }
        m0 = fmaxf(m0, leaky(acc0 + bs[lane]));
        m1 = fmaxf(m1, leaky(acc1 + bs[lane + 32]));
    }
    out[(size_t)node*64 + lane]      = m0;
    out[(size_t)node*64 + lane + 32] = m1;
}

// ---------------- 4) lin1 (133->512->256) + fused global max pool ------------
__global__ void k_lin(const float* __restrict__ wl1, const float* __restrict__ bl1,
                      const float* __restrict__ wl2, const float* __restrict__ bl2){
    __shared__ float CS[16][136];
    __shared__ float HS[16][512];
    int base = blockIdx.x*16;             // 16 nodes per block, same graph
    int b = base / NN;
    int t = threadIdx.x;                  // 256 threads

    for (int idx = t; idx < 16*133; idx += 256){
        int m = idx / 133, d = idx % 133;
        int node = base + m;
        float v;
        if (d < 5)        v = g_xx[node*5 + d];
        else if (d < 69)  v = g_x1[(size_t)node*64 + d - 5];
        else              v = g_x2[(size_t)node*64 + d - 69];
        CS[m][d] = v;
    }
    __syncthreads();

    // layer 1: each thread owns channels t and t+256
    float acc0[16], acc1[16];
    #pragma unroll
    for (int m = 0; m < 16; m++){ acc0[m] = 0.f; acc1[m] = 0.f; }
    for (int d = 0; d < 133; d++){
        float w0 = wl1[d*512 + t];
        float w1 = wl1[d*512 + t + 256];
        #pragma unroll
        for (int m = 0; m < 16; m++){
            float v = CS[m][d];
            acc0[m] += v*w0;
            acc1[m] += v*w1;
        }
    }
    float bb0 = bl1[t], bb1 = bl1[t + 256];
    #pragma unroll
    for (int m = 0; m < 16; m++){
        HS[m][t]       = leaky(acc0[m] + bb0);
        HS[m][t + 256] = leaky(acc1[m] + bb1);
    }
    __syncthreads();

    // layer 2: each thread owns channel t (no activation), then local max -> atomic
    float acc[16];
    #pragma unroll
    for (int m = 0; m < 16; m++) acc[m] = 0.f;
    for (int d = 0; d < 512; d++){
        float w = wl2[d*256 + t];
        #pragma unroll
        for (int m = 0; m < 16; m++) acc[m] += HS[m][d]*w;
    }
    float bb = bl2[t];
    float mx = -3.4e38f;
    #pragma unroll
    for (int m = 0; m < 16; m++) mx = fmaxf(mx, acc[m] + bb);
    atomicMaxFloat(&g_pool[b*256 + t], mx);
}

// ---------------- 5) head: leaky -> 256x128 -> leaky -> 128x3 ----------------
__global__ void k_head(const float* __restrict__ wm1, const float* __restrict__ bm1,
                       const float* __restrict__ wm2, const float* __restrict__ bm2,
                       float* __restrict__ out){
    __shared__ float gs[256];
    __shared__ float ms[128];
    int b = blockIdx.x, t = threadIdx.x;   // 128 threads
    for (int c = t; c < 256; c += 128) gs[c] = leaky(g_pool[b*256 + c]);
    __syncthreads();
    float acc = bm1[t];
    #pragma unroll 8
    for (int d = 0; d < 256; d++) acc += gs[d]*wm1[d*128 + t];
    ms[t] = leaky(acc);
    __syncthreads();
    if (t < 3){
        float o = bm2[t];
        #pragma unroll 8
        for (int d = 0; d < 128; d++) o += ms[d]*wm2[d*3 + t];
        out[b*3 + t] = o;
    }
}

// -----------------------------------------------------------------------------
extern "C" void kernel_launch(void* const* d_in, const int* in_sizes, int n_in,
                              void* d_out, int out_size){
    const float* x   = (const float*)d_in[0];
    const float* pos = (const float*)d_in[1];
    const float* tq  = (const float*)d_in[2];
    // d_in[3] = batch (unused: graphs are contiguous, equal-sized)
    const float* w1a = (const float*)d_in[4];
    const float* b1a = (const float*)d_in[5];
    const float* w1b = (const float*)d_in[6];
    const float* b1b = (const float*)d_in[7];
    const float* w2a = (const float*)d_in[8];
    const float* b2a = (const float*)d_in[9];
    const float* w2b = (const float*)d_in[10];
    const float* b2b = (const float*)d_in[11];
    const float* wl1 = (const float*)d_in[12];
    const float* bl1 = (const float*)d_in[13];
    const float* wl2 = (const float*)d_in[14];
    const float* bl2 = (const float*)d_in[15];
    const float* wm1 = (const float*)d_in[16];
    const float* bm1 = (const float*)d_in[17];
    const float* wm2 = (const float*)d_in[18];
    const float* bm2 = (const float*)d_in[19];
    float* out = (float*)d_out;

    k_build<<<BN/256, 256>>>(x, pos, tq);
    k_initpool<<<(BATCH*256)/256, 256>>>();

    // conv1: kNN on xx (d=5), factored layer-1, edge layer-2 + max
    k_knn<5><<<BATCH*(NN/8), 256>>>();
    k_convA<5, 64><<<(BN*64)/256, 256>>>(w1a, b1a);
    k_edge<64><<<BN/8, 256>>>(w1b, b1b);

    // conv2: kNN on x1 (d=64), factored layer-1, edge layer-2 + max
    k_knn<64><<<BATCH*(NN/8), 256>>>();
    k_convA<64, 128><<<(BN*128)/256, 256>>>(w2a, b2a);
    k_edge<128><<<BN/8, 256>>>(w2b, b2b);

    // lin1 + fused global max pool, then head
    k_lin<<<BN/16, 256>>>(wl1, bl1, wl2, bl2);
    k_head<<<BATCH, 128>>>(wm1, bm1, wm2, bm2, out);
}

// round 3
// speedup vs baseline: 1.5461x; 1.5461x over previous
#include <cuda_runtime.h>
#include <cuda_bf16.h>
#include <cstdint>

#define BATCH 128
#define NN    512
#define KNB   16
#define BN    (BATCH*NN)
#define NEGS  0.01f

// ---------------- scratch (device globals; no allocation allowed) -------------
__device__ float g_xx[BN*5];
__device__ float g_x1[BN*64];
__device__ float g_x2[BN*64];
__device__ int   g_idx[BN*KNB];
__device__ float g_A[(size_t)BN*128];
__device__ float g_C[(size_t)BN*128];
__device__ float g_pool[BATCH*256];
__device__ float g_sq[BN];
__device__ float g_d2[(size_t)BN*NN];

__device__ __forceinline__ float leaky(float v){ return v > 0.f ? v : NEGS*v; }

__device__ __forceinline__ void atomicMaxFloat(float* addr, float value){
    if (value >= 0.f) atomicMax((int*)addr, __float_as_int(value));
    else              atomicMin((unsigned int*)addr, __float_as_uint(value));
}

// ---------------- 0) build xx = [tq, x, pos] ---------------------------------
__global__ void k_build(const float* __restrict__ x, const float* __restrict__ pos,
                        const float* __restrict__ tq){
    int i = blockIdx.x*blockDim.x + threadIdx.x;
    if (i < BN){
        g_xx[i*5+0] = tq[i];
        g_xx[i*5+1] = x[i];
        g_xx[i*5+2] = pos[i*3+0];
        g_xx[i*5+3] = pos[i*3+1];
        g_xx[i*5+4] = pos[i*3+2];
    }
}

__global__ void k_initpool(){
    int i = blockIdx.x*blockDim.x + threadIdx.x;
    if (i < BATCH*256) g_pool[i] = __int_as_float(0xff800000); // -inf
}

// ---------------- 1a) kNN d=5 (cheap, fused compute+select) ------------------
__global__ void k_knn5(){
    const int D = 5, TILE = 128, PAD = D + 1;
    __shared__ float tile[TILE*PAD];
    __shared__ float sqs[TILE];
    __shared__ float fi[8][D];
    __shared__ float fsq[8];

    int b  = blockIdx.x >> 6;
    int q0 = (blockIdx.x & 63) * 8;
    int warp = threadIdx.x >> 5, lane = threadIdx.x & 31;
    int qi = q0 + warp;
    const float* Fb = g_xx + (size_t)b*NN*D;

    for (int d = lane; d < D; d += 32) fi[warp][d] = Fb[qi*D + d];
    __syncwarp();
    if (lane == 0){
        float s = 0.f;
        #pragma unroll
        for (int d = 0; d < D; d++) s += fi[warp][d]*fi[warp][d];
        fsq[warp] = s;
    }
    __syncwarp();
    float sqi = fsq[warp];

    float d2loc[16];
    for (int t = 0; t < NN/TILE; t++){
        __syncthreads();
        for (int idx = threadIdx.x; idx < TILE*D; idx += 256){
            int r = idx / D, c = idx % D;
            tile[r*PAD + c] = Fb[(t*TILE + r)*D + c];
        }
        __syncthreads();
        if (threadIdx.x < TILE){
            float s = 0.f;
            #pragma unroll
            for (int d = 0; d < D; d++){
                float v = tile[threadIdx.x*PAD + d];
                s += v*v;
            }
            sqs[threadIdx.x] = s;
        }
        __syncthreads();
        #pragma unroll
        for (int u = 0; u < TILE/32; u++){
            int jj = u*32 + lane;
            float dot = 0.f;
            #pragma unroll
            for (int d = 0; d < D; d++) dot += fi[warp][d]*tile[jj*PAD + d];
            d2loc[t*(TILE/32) + u] = sqi + sqs[jj] - 2.f*dot;
        }
    }

    int* myidx = g_idx + ((size_t)b*NN + qi)*KNB;
    for (int r = 0; r < KNB; r++){
        float bv = 3.0e38f; int bj = 0x7fffffff;
        #pragma unroll
        for (int u = 0; u < 16; u++){
            int j = u*32 + lane;
            float v = d2loc[u];
            if (v < bv || (v == bv && j < bj)){ bv = v; bj = j; }
        }
        #pragma unroll
        for (int off = 16; off > 0; off >>= 1){
            float ov = __shfl_xor_sync(0xffffffffu, bv, off);
            int   oj = __shfl_xor_sync(0xffffffffu, bj, off);
            if (ov < bv || (ov == bv && oj < bj)){ bv = ov; bj = oj; }
        }
        if (lane == 0) myidx[r] = bj;
        if (lane == (bj & 31)){
            #pragma unroll
            for (int u = 0; u < 16; u++) if (u == (bj >> 5)) d2loc[u] = 3.4e38f;
        }
    }
}

// ---------------- 1b) kNN d=64: row norms ------------------------------------
__global__ void k_sq(){
    int warp = threadIdx.x >> 5, lane = threadIdx.x & 31;
    int row = blockIdx.x*8 + warp;
    float2 v = ((const float2*)(g_x1 + (size_t)row*64))[lane];
    float s = v.x*v.x + v.y*v.y;
    #pragma unroll
    for (int off = 16; off > 0; off >>= 1) s += __shfl_xor_sync(0xffffffffu, s, off);
    if (lane == 0) g_sq[row] = s;
}

// ---------------- 1c) kNN d=64: pairwise d2 as register-blocked GEMM ---------
// block computes a 128x128 tile of d2 for one graph; 256 threads, 8x8 micro-tile
// K-chunked (2 x 32) so static smem stays at 33 KB (no opt-in attribute needed).
__global__ void k_d2(){
    __shared__ float As[32*132];   // As[k][m], k in chunk
    __shared__ float Bs[32*132];
    int b  = blockIdx.z;
    int i0 = blockIdx.y*128, j0 = blockIdx.x*128;
    const float* Fb = g_x1 + (size_t)b*NN*64;
    int t = threadIdx.x;
    int tx = t & 15, ty = t >> 4;
    int mi = ty*8, nj = tx*8;

    float acc[8][8];
    #pragma unroll
    for (int r = 0; r < 8; r++)
        #pragma unroll
        for (int c = 0; c < 8; c++) acc[r][c] = 0.f;

    for (int kb = 0; kb < 64; kb += 32){
        __syncthreads();
        for (int idx = t; idx < 128*32; idx += 256){
            int m = idx >> 5, k = idx & 31;
            As[k*132 + m] = Fb[(i0+m)*64 + kb + k];
            Bs[k*132 + m] = Fb[(j0+m)*64 + kb + k];
        }
        __syncthreads();
        #pragma unroll 4
        for (int k = 0; k < 32; k++){
            float4 a0 = *(const float4*)&As[k*132 + mi];
            float4 a1 = *(const float4*)&As[k*132 + mi + 4];
            float4 b0 = *(const float4*)&Bs[k*132 + nj];
            float4 b1 = *(const float4*)&Bs[k*132 + nj + 4];
            float a[8] = {a0.x,a0.y,a0.z,a0.w,a1.x,a1.y,a1.z,a1.w};
            float bb[8] = {b0.x,b0.y,b0.z,b0.w,b1.x,b1.y,b1.z,b1.w};
            #pragma unroll
            for (int r = 0; r < 8; r++)
                #pragma unroll
                for (int c = 0; c < 8; c++) acc[r][c] += a[r]*bb[c];
        }
    }

    float sqi[8], sqj[8];
    #pragma unroll
    for (int r = 0; r < 8; r++) sqi[r] = g_sq[b*NN + i0 + mi + r];
    #pragma unroll
    for (int c = 0; c < 8; c++) sqj[c] = g_sq[b*NN + j0 + nj + c];

    #pragma unroll
    for (int r = 0; r < 8; r++){
        float4 o0, o1;
        o0.x = sqi[r]+sqj[0]-2.f*acc[r][0]; o0.y = sqi[r]+sqj[1]-2.f*acc[r][1];
        o0.z = sqi[r]+sqj[2]-2.f*acc[r][2]; o0.w = sqi[r]+sqj[3]-2.f*acc[r][3];
        o1.x = sqi[r]+sqj[4]-2.f*acc[r][4]; o1.y = sqi[r]+sqj[5]-2.f*acc[r][5];
        o1.z = sqi[r]+sqj[6]-2.f*acc[r][6]; o1.w = sqi[r]+sqj[7]-2.f*acc[r][7];
        float* orow = g_d2 + ((size_t)(b*NN + i0 + mi + r))*NN + j0 + nj;
        *(float4*)orow = o0;
        *(float4*)(orow+4) = o1;
    }
}

// ---------------- 1d) kNN d=64: top-16 select from d2 row --------------------
__global__ void k_select(){
    int warp = threadIdx.x >> 5, lane = threadIdx.x & 31;
    int node = blockIdx.x*8 + warp;
    const float* row = g_d2 + (size_t)node*NN;
    float v[16];
    #pragma unroll
    for (int u4 = 0; u4 < 4; u4++){
        float4 x = *(const float4*)(row + lane*16 + u4*4);
        v[u4*4+0] = x.x; v[u4*4+1] = x.y; v[u4*4+2] = x.z; v[u4*4+3] = x.w;
    }
    int* myidx = g_idx + (size_t)node*KNB;
    for (int r = 0; r < KNB; r++){
        float bv = 3.0e38f; int bj = 0x7fffffff;
        #pragma unroll
        for (int u = 0; u < 16; u++){
            int j = lane*16 + u;
            float val = v[u];
            if (val < bv || (val == bv && j < bj)){ bv = val; bj = j; }
        }
        #pragma unroll
        for (int off = 16; off > 0; off >>= 1){
            float ov = __shfl_xor_sync(0xffffffffu, bv, off);
            int   oj = __shfl_xor_sync(0xffffffffu, bj, off);
            if (ov < bv || (ov == bv && oj < bj)){ bv = ov; bj = oj; }
        }
        if (lane == 0) myidx[r] = bj;
        if (lane == (bj >> 4)){
            #pragma unroll
            for (int u = 0; u < 16; u++) if (u == (bj & 15)) v[u] = 3.4e38f;
        }
    }
}

// ---------------- 2a) conv1 layer-1 factorization (d=5, H=64) ----------------
// A[i] = xi @ (W_top - W_bot) + b ;  C[j] = xj @ W_bot
__global__ void k_convA1(const float* __restrict__ W, const float* __restrict__ bias){
    int t = blockIdx.x*blockDim.x + threadIdx.x;
    if (t >= BN*64) return;
    int i = t >> 6, c = t & 63;
    const float* f = g_xx + (size_t)i*5;
    float a = bias[c], cc = 0.f;
    #pragma unroll
    for (int d = 0; d < 5; d++){
        float v  = f[d];
        float wt = W[d*64 + c];
        float wb = W[(5 + d)*64 + c];
        a  += v*(wt - wb);
        cc += v*wb;
    }
    g_A[(size_t)i*64 + c] = a;
    g_C[(size_t)i*64 + c] = cc;
}

// ---------------- 2b) conv2 layer-1 (d=64, H=128), d-chunked smem weights ----
__global__ void k_convA2(const float* __restrict__ W, const float* __restrict__ bias){
    __shared__ float Wd[32*128];   // (W_top - W_bot) chunk
    __shared__ float Wb[32*128];   // W_bot chunk
    __shared__ float Fs[16*64];
    int t = threadIdx.x;           // 256
    int base = blockIdx.x*16;

    for (int idx = t; idx < 1024; idx += 256)
        Fs[idx] = g_x1[(size_t)base*64 + idx];

    int m  = t >> 4;
    int cg = (t & 15)*8;
    float a[8], cc[8];
    float4 bb0 = *(const float4*)(bias + cg);
    float4 bb1 = *(const float4*)(bias + cg + 4);
    a[0]=bb0.x; a[1]=bb0.y; a[2]=bb0.z; a[3]=bb0.w;
    a[4]=bb1.x; a[5]=bb1.y; a[6]=bb1.z; a[7]=bb1.w;
    #pragma unroll
    for (int q = 0; q < 8; q++) cc[q] = 0.f;

    for (int db = 0; db < 64; db += 32){
        __syncthreads();
        for (int idx = t; idx < 4096; idx += 256){
            int d = idx >> 7, c = idx & 127;
            float wt = W[(db + d)*128 + c];
            float wb = W[(64 + db + d)*128 + c];
            Wd[idx] = wt - wb;
            Wb[idx] = wb;
        }
        __syncthreads();
        #pragma unroll 4
        for (int d = 0; d < 32; d++){
            float v = Fs[m*64 + db + d];
            float4 w0 = *(const float4*)&Wd[d*128 + cg];
            float4 w1 = *(const float4*)&Wd[d*128 + cg + 4];
            float4 u0 = *(const float4*)&Wb[d*128 + cg];
            float4 u1 = *(const float4*)&Wb[d*128 + cg + 4];
            a[0] += v*w0.x; a[1] += v*w0.y; a[2] += v*w0.z; a[3] += v*w0.w;
            a[4] += v*w1.x; a[5] += v*w1.y; a[6] += v*w1.z; a[7] += v*w1.w;
            cc[0] += v*u0.x; cc[1] += v*u0.y; cc[2] += v*u0.z; cc[3] += v*u0.w;
            cc[4] += v*u1.x; cc[5] += v*u1.y; cc[6] += v*u1.z; cc[7] += v*u1.w;
        }
    }
    int node = base + m;
    float4* pa = (float4*)(g_A + (size_t)node*128 + cg);
    float4* pc = (float4*)(g_C + (size_t)node*128 + cg);
    pa[0] = make_float4(a[0],a[1],a[2],a[3]);
    pa[1] = make_float4(a[4],a[5],a[6],a[7]);
    pc[0] = make_float4(cc[0],cc[1],cc[2],cc[3]);
    pc[1] = make_float4(cc[4],cc[5],cc[6],cc[7]);
}

// ---------------- 3) edge MLP layer-2 + max over K, register-tiled -----------
// 4 warps/block, one node per warp: build h[16][H] in smem, then 16xH @ Hx64
// with 32 register accumulators. Ws staged in chunks of CH rows (<=48KB static).
template<int H>
__global__ void k_edge2(const float* __restrict__ W, const float* __restrict__ bias){
    const int CH = (H == 128) ? 32 : 64;      // weight chunk rows
    __shared__ float Ws[CH*64];
    __shared__ float hs[4*16*H];
    int t = threadIdx.x;                      // 128 threads
    int warp = t >> 5, lane = t & 31;
    int node = blockIdx.x*4 + warp;
    int b = node / NN;
    float* hw = hs + warp*16*H;
    float* out = (H == 64) ? g_x1 : g_x2;

    int jv = 0;
    if (lane < 16) jv = g_idx[(size_t)node*KNB + lane];

    if (H == 128){
        float4 a4 = *(const float4*)(g_A + (size_t)node*128 + lane*4);
        #pragma unroll 4
        for (int m = 0; m < 16; m++){
            int j = b*NN + __shfl_sync(0xffffffffu, jv, m);
            float4 c4 = *(const float4*)(g_C + (size_t)j*128 + lane*4);
            float4 h;
            h.x = leaky(a4.x + c4.x); h.y = leaky(a4.y + c4.y);
            h.z = leaky(a4.z + c4.z); h.w = leaky(a4.w + c4.w);
            *(float4*)&hw[m*128 + lane*4] = h;
        }
    } else {
        float2 a2 = *(const float2*)(g_A + (size_t)node*64 + lane*2);
        #pragma unroll 4
        for (int m = 0; m < 16; m++){
            int j = b*NN + __shfl_sync(0xffffffffu, jv, m);
            float2 c2 = *(const float2*)(g_C + (size_t)j*64 + lane*2);
            float2 h;
            h.x = leaky(a2.x + c2.x); h.y = leaky(a2.y + c2.y);
            *(float2*)&hw[m*64 + lane*2] = h;
        }
    }

    float acc0[16], acc1[16];
    #pragma unroll
    for (int m = 0; m < 16; m++){ acc0[m] = 0.f; acc1[m] = 0.f; }

    for (int cb = 0; cb < H; cb += CH){
        __syncthreads();                      // also covers the hs build on iter 0
        for (int i = t; i < CH*64; i += 128) Ws[i] = W[cb*64 + i];
        __syncthreads();
        #pragma unroll
        for (int g = 0; g < CH/4; g++){
            int kk = g*4;
            float w00 = Ws[(kk+0)*64 + lane],      w01 = Ws[(kk+1)*64 + lane];
            float w02 = Ws[(kk+2)*64 + lane],      w03 = Ws[(kk+3)*64 + lane];
            float w10 = Ws[(kk+0)*64 + lane + 32], w11 = Ws[(kk+1)*64 + lane + 32];
            float w12 = Ws[(kk+2)*64 + lane + 32], w13 = Ws[(kk+3)*64 + lane + 32];
            #pragma unroll
            for (int m = 0; m < 16; m++){
                float4 h4 = *(const float4*)&hw[m*H + cb + kk];
                acc0[m] += h4.x*w00; acc0[m] += h4.y*w01;
                acc0[m] += h4.z*w02; acc0[m] += h4.w*w03;
                acc1[m] += h4.x*w10; acc1[m] += h4.y*w11;
                acc1[m] += h4.z*w12; acc1[m] += h4.w*w13;
            }
        }
    }

    float m0 = -3.4e38f, m1 = -3.4e38f;
    #pragma unroll
    for (int m = 0; m < 16; m++){ m0 = fmaxf(m0, acc0[m]); m1 = fmaxf(m1, acc1[m]); }
    // leaky is monotone increasing: max, then bias, then leaky
    out[(size_t)node*64 + lane]      = leaky(m0 + bias[lane]);
    out[(size_t)node*64 + lane + 32] = leaky(m1 + bias[lane + 32]);
}

// ---------------- 4) lin1 (133->512->256) + fused global max pool ------------
__global__ void k_lin(const float* __restrict__ wl1, const float* __restrict__ bl1,
                      const float* __restrict__ wl2, const float* __restrict__ bl2){
    __shared__ float CS[16][136];
    __shared__ float HS[16][512];
    int base = blockIdx.x*16;
    int b = base / NN;
    int t = threadIdx.x;

    for (int idx = t; idx < 16*133; idx += 256){
        int m = idx / 133, d = idx % 133;
        int node = base + m;
        float v;
        if (d < 5)        v = g_xx[node*5 + d];
        else if (d < 69)  v = g_x1[(size_t)node*64 + d - 5];
        else              v = g_x2[(size_t)node*64 + d - 69];
        CS[m][d] = v;
    }
    __syncthreads();

    float acc0[16], acc1[16];
    #pragma unroll
    for (int m = 0; m < 16; m++){ acc0[m] = 0.f; acc1[m] = 0.f; }
    for (int d4 = 0; d4 < 132; d4 += 4){
        float wa0 = wl1[(d4+0)*512 + t],       wa1 = wl1[(d4+1)*512 + t];
        float wa2 = wl1[(d4+2)*512 + t],       wa3 = wl1[(d4+3)*512 + t];
        float wb0 = wl1[(d4+0)*512 + t + 256], wb1 = wl1[(d4+1)*512 + t + 256];
        float wb2 = wl1[(d4+2)*512 + t + 256], wb3 = wl1[(d4+3)*512 + t + 256];
        #pragma unroll
        for (int m = 0; m < 16; m++){
            float4 v = *(const float4*)&CS[m][d4];
            acc0[m] += v.x*wa0; acc0[m] += v.y*wa1;
            acc0[m] += v.z*wa2; acc0[m] += v.w*wa3;
            acc1[m] += v.x*wb0; acc1[m] += v.y*wb1;
            acc1[m] += v.z*wb2; acc1[m] += v.w*wb3;
        }
    }
    {   // remainder d = 132
        float wa = wl1[132*512 + t], wb = wl1[132*512 + t + 256];
        #pragma unroll
        for (int m = 0; m < 16; m++){
            float v = CS[m][132];
            acc0[m] += v*wa; acc1[m] += v*wb;
        }
    }
    float bb0 = bl1[t], bb1 = bl1[t + 256];
    #pragma unroll
    for (int m = 0; m < 16; m++){
        HS[m][t]       = leaky(acc0[m] + bb0);
        HS[m][t + 256] = leaky(acc1[m] + bb1);
    }
    __syncthreads();

    float acc[16];
    #pragma unroll
    for (int m = 0; m < 16; m++) acc[m] = 0.f;
    for (int d4 = 0; d4 < 512; d4 += 4){
        float w0 = wl2[(d4+0)*256 + t], w1 = wl2[(d4+1)*256 + t];
        float w2 = wl2[(d4+2)*256 + t], w3 = wl2[(d4+3)*256 + t];
        #pragma unroll
        for (int m = 0; m < 16; m++){
            float4 h = *(const float4*)&HS[m][d4];
            acc[m] += h.x*w0; acc[m] += h.y*w1;
            acc[m] += h.z*w2; acc[m] += h.w*w3;
        }
    }
    float bb = bl2[t];
    float mx = -3.4e38f;
    #pragma unroll
    for (int m = 0; m < 16; m++) mx = fmaxf(mx, acc[m] + bb);
    atomicMaxFloat(&g_pool[b*256 + t], mx);
}

// ---------------- 5) head: leaky -> 256x128 -> leaky -> 128x3 ----------------
__global__ void k_head(const float* __restrict__ wm1, const float* __restrict__ bm1,
                       const float* __restrict__ wm2, const float* __restrict__ bm2,
                       float* __restrict__ out){
    __shared__ float gs[256];
    __shared__ float ms[128];
    int b = blockIdx.x, t = threadIdx.x;
    for (int c = t; c < 256; c += 128) gs[c] = leaky(g_pool[b*256 + c]);
    __syncthreads();
    float acc = bm1[t];
    #pragma unroll 8
    for (int d = 0; d < 256; d++) acc += gs[d]*wm1[d*128 + t];
    ms[t] = leaky(acc);
    __syncthreads();
    if (t < 3){
        float o = bm2[t];
        #pragma unroll 8
        for (int d = 0; d < 128; d++) o += ms[d]*wm2[d*3 + t];
        out[b*3 + t] = o;
    }
}

// -----------------------------------------------------------------------------
extern "C" void kernel_launch(void* const* d_in, const int* in_sizes, int n_in,
                              void* d_out, int out_size){
    const float* x   = (const float*)d_in[0];
    const float* pos = (const float*)d_in[1];
    const float* tq  = (const float*)d_in[2];
    const float* w1a = (const float*)d_in[4];
    const float* b1a = (const float*)d_in[5];
    const float* w1b = (const float*)d_in[6];
    const float* b1b = (const float*)d_in[7];
    const float* w2a = (const float*)d_in[8];
    const float* b2a = (const float*)d_in[9];
    const float* w2b = (const float*)d_in[10];
    const float* b2b = (const float*)d_in[11];
    const float* wl1 = (const float*)d_in[12];
    const float* bl1 = (const float*)d_in[13];
    const float* wl2 = (const float*)d_in[14];
    const float* bl2 = (const float*)d_in[15];
    const float* wm1 = (const float*)d_in[16];
    const float* bm1 = (const float*)d_in[17];
    const float* wm2 = (const float*)d_in[18];
    const float* bm2 = (const float*)d_in[19];
    float* out = (float*)d_out;

    k_build<<<BN/256, 256>>>(x, pos, tq);
    k_initpool<<<(BATCH*256)/256, 256>>>();

    // conv1
    k_knn5<<<BATCH*(NN/8), 256>>>();
    k_convA1<<<(BN*64)/256, 256>>>(w1a, b1a);
    k_edge2<64><<<BN/4, 128>>>(w1b, b1b);

    // conv2
    k_sq<<<BN/8, 256>>>();
    {
        dim3 grid(4, 4, BATCH);
        k_d2<<<grid, 256>>>();
    }
    k_select<<<BN/8, 256>>>();
    k_convA2<<<BN/16, 256>>>(w2a, b2a);
    k_edge2<128><<<BN/4, 128>>>(w2b, b2b);

    // lin1 + pool + head
    k_lin<<<BN/16, 256>>>(wl1, bl1, wl2, bl2);
    k_head<<<BATCH, 128>>>(wm1, bm1, wm2, bm2, out);
}

// round 4
// speedup vs baseline: 1.6589x; 1.0729x over previous
#include <cuda_runtime.h>
#include <cuda_bf16.h>
#include <cstdint>

#define BATCH 128
#define NN    512
#define KNB   16
#define BN    (BATCH*NN)
#define NEGS  0.01f

// ---------------- scratch (device globals; no allocation allowed) -------------
__device__ float g_xx[BN*5];
__device__ float g_x1[BN*64];
__device__ float g_x2[BN*64];
__device__ int   g_idx[BN*KNB];
__device__ float g_A[(size_t)BN*128];
__device__ float g_C[(size_t)BN*128];
__device__ float g_pool[BATCH*256];
__device__ float g_sq[BN];
__device__ float g_d2[(size_t)BN*NN];   // reused as HS buffer after k_select

// split-TF32 weight copies
__device__ float g_w1b_h[64*64],   g_w1b_l[64*64];
__device__ float g_w2b_h[128*64],  g_w2b_l[128*64];
__device__ float g_wl1_h[136*512], g_wl1_l[136*512];
__device__ float g_wl2_h[512*256], g_wl2_l[512*256];

__device__ __forceinline__ float leaky(float v){ return v > 0.f ? v : NEGS*v; }

__device__ __forceinline__ void atomicMaxFloat(float* addr, float value){
    if (value >= 0.f) atomicMax((int*)addr, __float_as_int(value));
    else              atomicMin((unsigned int*)addr, __float_as_uint(value));
}

__device__ __forceinline__ unsigned f2tf(float x){
    unsigned u; asm("cvt.rna.tf32.f32 %0, %1;" : "=r"(u) : "f"(x)); return u;
}
__device__ __forceinline__ void splt(float x, unsigned &h, unsigned &l){
    h = f2tf(x);
    l = f2tf(x - __uint_as_float(h));
}
__device__ __forceinline__ void mma8(float* c, const unsigned* a, const unsigned* b){
    asm("mma.sync.aligned.m16n8k8.row.col.f32.tf32.tf32.f32 "
        "{%0,%1,%2,%3}, {%4,%5,%6,%7}, {%8,%9}, {%0,%1,%2,%3};"
        : "+f"(c[0]), "+f"(c[1]), "+f"(c[2]), "+f"(c[3])
        : "r"(a[0]), "r"(a[1]), "r"(a[2]), "r"(a[3]), "r"(b[0]), "r"(b[1]));
}

// ---------------- prep: split weights into tf32 hi/lo ------------------------
__global__ void k_prep(const float* __restrict__ w1b, const float* __restrict__ w2b,
                       const float* __restrict__ wl1, const float* __restrict__ wl2){
    int i = blockIdx.x*256 + threadIdx.x;
    float v; float *ph, *pl;
    if (i < 4096){ v = w1b[i]; ph = g_w1b_h + i; pl = g_w1b_l + i; }
    else if (i < 12288){ int j = i - 4096; v = w2b[j]; ph = g_w2b_h + j; pl = g_w2b_l + j; }
    else if (i < 81920){
        int j = i - 12288; int k = j >> 9, c = j & 511;
        v = (k < 133) ? wl1[k*512 + c] : 0.f;
        ph = g_wl1_h + j; pl = g_wl1_l + j;
    }
    else if (i < 212992){ int j = i - 81920; v = wl2[j]; ph = g_wl2_h + j; pl = g_wl2_l + j; }
    else return;
    unsigned hi = f2tf(v);
    float lo = v - __uint_as_float(hi);
    *ph = __uint_as_float(hi);
    *pl = __uint_as_float(f2tf(lo));
}

// ---------------- 0) build xx = [tq, x, pos] ---------------------------------
__global__ void k_build(const float* __restrict__ x, const float* __restrict__ pos,
                        const float* __restrict__ tq){
    int i = blockIdx.x*blockDim.x + threadIdx.x;
    if (i < BN){
        g_xx[i*5+0] = tq[i];
        g_xx[i*5+1] = x[i];
        g_xx[i*5+2] = pos[i*3+0];
        g_xx[i*5+3] = pos[i*3+1];
        g_xx[i*5+4] = pos[i*3+2];
    }
}

__global__ void k_initpool(){
    int i = blockIdx.x*blockDim.x + threadIdx.x;
    if (i < BATCH*256) g_pool[i] = __int_as_float(0xff800000); // -inf
}

// ---------------- 1a) kNN d=5 (cheap, fused compute+select) ------------------
__global__ void k_knn5(){
    const int D = 5, TILE = 128, PAD = D + 1;
    __shared__ float tile[TILE*PAD];
    __shared__ float sqs[TILE];
    __shared__ float fi[8][D];
    __shared__ float fsq[8];

    int b  = blockIdx.x >> 6;
    int q0 = (blockIdx.x & 63) * 8;
    int warp = threadIdx.x >> 5, lane = threadIdx.x & 31;
    int qi = q0 + warp;
    const float* Fb = g_xx + (size_t)b*NN*D;

    for (int d = lane; d < D; d += 32) fi[warp][d] = Fb[qi*D + d];
    __syncwarp();
    if (lane == 0){
        float s = 0.f;
        #pragma unroll
        for (int d = 0; d < D; d++) s += fi[warp][d]*fi[warp][d];
        fsq[warp] = s;
    }
    __syncwarp();
    float sqi = fsq[warp];

    float d2loc[16];
    for (int t = 0; t < NN/TILE; t++){
        __syncthreads();
        for (int idx = threadIdx.x; idx < TILE*D; idx += 256){
            int r = idx / D, c = idx % D;
            tile[r*PAD + c] = Fb[(t*TILE + r)*D + c];
        }
        __syncthreads();
        if (threadIdx.x < TILE){
            float s = 0.f;
            #pragma unroll
            for (int d = 0; d < D; d++){
                float v = tile[threadIdx.x*PAD + d];
                s += v*v;
            }
            sqs[threadIdx.x] = s;
        }
        __syncthreads();
        #pragma unroll
        for (int u = 0; u < TILE/32; u++){
            int jj = u*32 + lane;
            float dot = 0.f;
            #pragma unroll
            for (int d = 0; d < D; d++) dot += fi[warp][d]*tile[jj*PAD + d];
            d2loc[t*(TILE/32) + u] = sqi + sqs[jj] - 2.f*dot;
        }
    }

    int* myidx = g_idx + ((size_t)b*NN + qi)*KNB;
    for (int r = 0; r < KNB; r++){
        float bv = 3.0e38f; int bj = 0x7fffffff;
        #pragma unroll
        for (int u = 0; u < 16; u++){
            int j = u*32 + lane;
            float v = d2loc[u];
            if (v < bv || (v == bv && j < bj)){ bv = v; bj = j; }
        }
        #pragma unroll
        for (int off = 16; off > 0; off >>= 1){
            float ov = __shfl_xor_sync(0xffffffffu, bv, off);
            int   oj = __shfl_xor_sync(0xffffffffu, bj, off);
            if (ov < bv || (ov == bv && oj < bj)){ bv = ov; bj = oj; }
        }
        if (lane == 0) myidx[r] = bj;
        if (lane == (bj & 31)){
            #pragma unroll
            for (int u = 0; u < 16; u++) if (u == (bj >> 5)) d2loc[u] = 3.4e38f;
        }
    }
}

// ---------------- 1b) kNN d=64: row norms ------------------------------------
__global__ void k_sq(){
    int warp = threadIdx.x >> 5, lane = threadIdx.x & 31;
    int row = blockIdx.x*8 + warp;
    float2 v = ((const float2*)(g_x1 + (size_t)row*64))[lane];
    float s = v.x*v.x + v.y*v.y;
    #pragma unroll
    for (int off = 16; off > 0; off >>= 1) s += __shfl_xor_sync(0xffffffffu, s, off);
    if (lane == 0) g_sq[row] = s;
}

// ---------------- 1c) kNN d=64: pairwise d2 (fp32 register GEMM) -------------
__global__ void k_d2(){
    __shared__ float As[32*132];
    __shared__ float Bs[32*132];
    int b  = blockIdx.z;
    int i0 = blockIdx.y*128, j0 = blockIdx.x*128;
    const float* Fb = g_x1 + (size_t)b*NN*64;
    int t = threadIdx.x;
    int tx = t & 15, ty = t >> 4;
    int mi = ty*8, nj = tx*8;

    float acc[8][8];
    #pragma unroll
    for (int r = 0; r < 8; r++)
        #pragma unroll
        for (int c = 0; c < 8; c++) acc[r][c] = 0.f;

    for (int kb = 0; kb < 64; kb += 32){
        __syncthreads();
        for (int idx = t; idx < 128*32; idx += 256){
            int m = idx >> 5, k = idx & 31;
            As[k*132 + m] = Fb[(i0+m)*64 + kb + k];
            Bs[k*132 + m] = Fb[(j0+m)*64 + kb + k];
        }
        __syncthreads();
        #pragma unroll 4
        for (int k = 0; k < 32; k++){
            float4 a0 = *(const float4*)&As[k*132 + mi];
            float4 a1 = *(const float4*)&As[k*132 + mi + 4];
            float4 b0 = *(const float4*)&Bs[k*132 + nj];
            float4 b1 = *(const float4*)&Bs[k*132 + nj + 4];
            float a[8] = {a0.x,a0.y,a0.z,a0.w,a1.x,a1.y,a1.z,a1.w};
            float bb[8] = {b0.x,b0.y,b0.z,b0.w,b1.x,b1.y,b1.z,b1.w};
            #pragma unroll
            for (int r = 0; r < 8; r++)
                #pragma unroll
                for (int c = 0; c < 8; c++) acc[r][c] += a[r]*bb[c];
        }
    }

    float sqi[8], sqj[8];
    #pragma unroll
    for (int r = 0; r < 8; r++) sqi[r] = g_sq[b*NN + i0 + mi + r];
    #pragma unroll
    for (int c = 0; c < 8; c++) sqj[c] = g_sq[b*NN + j0 + nj + c];

    #pragma unroll
    for (int r = 0; r < 8; r++){
        float4 o0, o1;
        o0.x = sqi[r]+sqj[0]-2.f*acc[r][0]; o0.y = sqi[r]+sqj[1]-2.f*acc[r][1];
        o0.z = sqi[r]+sqj[2]-2.f*acc[r][2]; o0.w = sqi[r]+sqj[3]-2.f*acc[r][3];
        o1.x = sqi[r]+sqj[4]-2.f*acc[r][4]; o1.y = sqi[r]+sqj[5]-2.f*acc[r][5];
        o1.z = sqi[r]+sqj[6]-2.f*acc[r][6]; o1.w = sqi[r]+sqj[7]-2.f*acc[r][7];
        float* orow = g_d2 + ((size_t)(b*NN + i0 + mi + r))*NN + j0 + nj;
        *(float4*)orow = o0;
        *(float4*)(orow+4) = o1;
    }
}

// ---------------- 1d) kNN d=64: top-16 select --------------------------------
__global__ void k_select(){
    int warp = threadIdx.x >> 5, lane = threadIdx.x & 31;
    int node = blockIdx.x*8 + warp;
    const float* row = g_d2 + (size_t)node*NN;
    float v[16];
    #pragma unroll
    for (int u4 = 0; u4 < 4; u4++){
        float4 x = *(const float4*)(row + lane*16 + u4*4);
        v[u4*4+0] = x.x; v[u4*4+1] = x.y; v[u4*4+2] = x.z; v[u4*4+3] = x.w;
    }
    int* myidx = g_idx + (size_t)node*KNB;
    for (int r = 0; r < KNB; r++){
        float bv = 3.0e38f; int bj = 0x7fffffff;
        #pragma unroll
        for (int u = 0; u < 16; u++){
            int j = lane*16 + u;
            float val = v[u];
            if (val < bv || (val == bv && j < bj)){ bv = val; bj = j; }
        }
        #pragma unroll
        for (int off = 16; off > 0; off >>= 1){
            float ov = __shfl_xor_sync(0xffffffffu, bv, off);
            int   oj = __shfl_xor_sync(0xffffffffu, bj, off);
            if (ov < bv || (ov == bv && oj < bj)){ bv = ov; bj = oj; }
        }
        if (lane == 0) myidx[r] = bj;
        if (lane == (bj >> 4)){
            #pragma unroll
            for (int u = 0; u < 16; u++) if (u == (bj & 15)) v[u] = 3.4e38f;
        }
    }
}

// ---------------- 2a) conv1 layer-1 factorization (d=5, H=64) ----------------
__global__ void k_convA1(const float* __restrict__ W, const float* __restrict__ bias){
    int t = blockIdx.x*blockDim.x + threadIdx.x;
    if (t >= BN*64) return;
    int i = t >> 6, c = t & 63;
    const float* f = g_xx + (size_t)i*5;
    float a = bias[c], cc = 0.f;
    #pragma unroll
    for (int d = 0; d < 5; d++){
        float v  = f[d];
        float wt = W[d*64 + c];
        float wb = W[(5 + d)*64 + c];
        a  += v*(wt - wb);
        cc += v*wb;
    }
    g_A[(size_t)i*64 + c] = a;
    g_C[(size_t)i*64 + c] = cc;
}

// ---------------- 2b) conv2 layer-1 (d=64, H=128) ----------------------------
__global__ void k_convA2(const float* __restrict__ W, const float* __restrict__ bias){
    __shared__ float Wd[32*128];
    __shared__ float Wb[32*128];
    __shared__ float Fs[16*64];
    int t = threadIdx.x;
    int base = blockIdx.x*16;

    for (int idx = t; idx < 1024; idx += 256)
        Fs[idx] = g_x1[(size_t)base*64 + idx];

    int m  = t >> 4;
    int cg = (t & 15)*8;
    float a[8], cc[8];
    float4 bb0 = *(const float4*)(bias + cg);
    float4 bb1 = *(const float4*)(bias + cg + 4);
    a[0]=bb0.x; a[1]=bb0.y; a[2]=bb0.z; a[3]=bb0.w;
    a[4]=bb1.x; a[5]=bb1.y; a[6]=bb1.z; a[7]=bb1.w;
    #pragma unroll
    for (int q = 0; q < 8; q++) cc[q] = 0.f;

    for (int db = 0; db < 64; db += 32){
        __syncthreads();
        for (int idx = t; idx < 4096; idx += 256){
            int d = idx >> 7, c = idx & 127;
            float wt = W[(db + d)*128 + c];
            float wb = W[(64 + db + d)*128 + c];
            Wd[idx] = wt - wb;
            Wb[idx] = wb;
        }
        __syncthreads();
        #pragma unroll 4
        for (int d = 0; d < 32; d++){
            float v = Fs[m*64 + db + d];
            float4 w0 = *(const float4*)&Wd[d*128 + cg];
            float4 w1 = *(const float4*)&Wd[d*128 + cg + 4];
            float4 u0 = *(const float4*)&Wb[d*128 + cg];
            float4 u1 = *(const float4*)&Wb[d*128 + cg + 4];
            a[0] += v*w0.x; a[1] += v*w0.y; a[2] += v*w0.z; a[3] += v*w0.w;
            a[4] += v*w1.x; a[5] += v*w1.y; a[6] += v*w1.z; a[7] += v*w1.w;
            cc[0] += v*u0.x; cc[1] += v*u0.y; cc[2] += v*u0.z; cc[3] += v*u0.w;
            cc[4] += v*u1.x; cc[5] += v*u1.y; cc[6] += v*u1.z; cc[7] += v*u1.w;
        }
    }
    int node = base + m;
    float4* pa = (float4*)(g_A + (size_t)node*128 + cg);
    float4* pc = (float4*)(g_C + (size_t)node*128 + cg);
    pa[0] = make_float4(a[0],a[1],a[2],a[3]);
    pa[1] = make_float4(a[4],a[5],a[6],a[7]);
    pc[0] = make_float4(cc[0],cc[1],cc[2],cc[3]);
    pc[1] = make_float4(cc[4],cc[5],cc[6],cc[7]);
}

// ---------------- 3) edge MLP layer-2 + max over K — tensor cores ------------
// 4 warps/block, 1 node/warp. h[16][H] in smem (fp32, split on the fly),
// weights pre-split, staged in 16-row smem chunks. D = 16x64 via m16n8k8.
template<int H>
__global__ void k_edge2t(const float* __restrict__ bias){
    const int S = (H == 128) ? 132 : 68;     // conflict-free A stride (mod 32 == 4)
    __shared__ float hs[4*16*S];
    __shared__ float wsh[16*72];
    __shared__ float wsl[16*72];
    int t = threadIdx.x, warp = t >> 5, lane = t & 31;
    int node = blockIdx.x*4 + warp;
    int b = node / NN;
    float* hw = hs + warp*16*S;
    float* out = (H == 64) ? g_x1 : g_x2;
    const float* Wh = (H == 64) ? g_w1b_h : g_w2b_h;
    const float* Wl = (H == 64) ? g_w1b_l : g_w2b_l;

    int jv = 0;
    if (lane < 16) jv = g_idx[(size_t)node*KNB + lane];

    if (H == 128){
        float4 a4 = *(const float4*)(g_A + (size_t)node*128 + lane*4);
        #pragma unroll 4
        for (int m = 0; m < 16; m++){
            int j = b*NN + __shfl_sync(0xffffffffu, jv, m);
            float4 c4 = *(const float4*)(g_C + (size_t)j*128 + lane*4);
            float4 h;
            h.x = leaky(a4.x + c4.x); h.y = leaky(a4.y + c4.y);
            h.z = leaky(a4.z + c4.z); h.w = leaky(a4.w + c4.w);
            *(float4*)&hw[m*S + lane*4] = h;
        }
    } else {
        float2 a2 = *(const float2*)(g_A + (size_t)node*64 + lane*2);
        #pragma unroll 4
        for (int m = 0; m < 16; m++){
            int j = b*NN + __shfl_sync(0xffffffffu, jv, m);
            float2 c2 = *(const float2*)(g_C + (size_t)j*64 + lane*2);
            float2 h;
            h.x = leaky(a2.x + c2.x); h.y = leaky(a2.y + c2.y);
            *(float2*)&hw[m*S + lane*2] = h;
        }
    }
    __syncwarp();

    float acc[8][4];
    #pragma unroll
    for (int nt = 0; nt < 8; nt++)
        #pragma unroll
        for (int i = 0; i < 4; i++) acc[nt][i] = 0.f;

    int r = lane >> 2, q = lane & 3;
    for (int kb = 0; kb < H; kb += 16){
        __syncthreads();
        for (int i = t; i < 1024; i += 128){
            int rr = i >> 6, c = i & 63;
            wsh[rr*72 + c] = Wh[(kb + rr)*64 + c];
            wsl[rr*72 + c] = Wl[(kb + rr)*64 + c];
        }
        __syncthreads();
        #pragma unroll
        for (int ks = 0; ks < 16; ks += 8){
            int k0 = kb + ks;
            unsigned ah[4], al[4];
            splt(hw[r*S + k0 + q],           ah[0], al[0]);
            splt(hw[(r+8)*S + k0 + q],       ah[1], al[1]);
            splt(hw[r*S + k0 + q + 4],       ah[2], al[2]);
            splt(hw[(r+8)*S + k0 + q + 4],   ah[3], al[3]);
            #pragma unroll
            for (int nt = 0; nt < 8; nt++){
                int bo = (ks + q)*72 + nt*8 + r;
                unsigned bh[2] = {__float_as_uint(wsh[bo]), __float_as_uint(wsh[bo + 288])};
                unsigned bl[2] = {__float_as_uint(wsl[bo]), __float_as_uint(wsl[bo + 288])};
                mma8(acc[nt], ah, bh);
                mma8(acc[nt], ah, bl);
                mma8(acc[nt], al, bh);
            }
        }
    }

    // max over the 16 neighbor rows, then bias + leaky (monotone)
    #pragma unroll
    for (int nt = 0; nt < 8; nt++){
        float m0 = fmaxf(acc[nt][0], acc[nt][2]);
        float m1 = fmaxf(acc[nt][1], acc[nt][3]);
        #pragma unroll
        for (int off = 4; off < 32; off <<= 1){
            m0 = fmaxf(m0, __shfl_xor_sync(0xffffffffu, m0, off));
            m1 = fmaxf(m1, __shfl_xor_sync(0xffffffffu, m1, off));
        }
        if (lane < 4){
            int c = nt*8 + lane*2;
            out[(size_t)node*64 + c]     = leaky(m0 + __ldg(bias + c));
            out[(size_t)node*64 + c + 1] = leaky(m1 + __ldg(bias + c + 1));
        }
    }
}

// ---------------- 4a) lin1: [BN x 136] @ [136 x 512] + leaky -> g_d2 ---------
__global__ void k_lin1(const float* __restrict__ bl1){
    __shared__ float CS[64*140];
    int t = threadIdx.x, lane = t & 31, w = t >> 5;
    int base = blockIdx.x*64;
    for (int i = t; i < 64*136; i += 256){
        int m = i / 136, d = i - m*136;
        int node = base + m;
        float v = 0.f;
        if (d < 5)        v = g_xx[node*5 + d];
        else if (d < 69)  v = g_x1[(size_t)node*64 + d - 5];
        else if (d < 133) v = g_x2[(size_t)node*64 + d - 69];
        CS[m*140 + d] = v;
    }
    __syncthreads();

    int r = lane >> 2, q = lane & 3;
    int n0 = w*64;
    for (int np = 0; np < 2; np++){
        float acc[4][4][4];
        #pragma unroll
        for (int mt = 0; mt < 4; mt++)
            #pragma unroll
            for (int nt = 0; nt < 4; nt++)
                #pragma unroll
                for (int i = 0; i < 4; i++) acc[mt][nt][i] = 0.f;

        for (int k0 = 0; k0 < 136; k0 += 8){
            unsigned ah[4][4], al[4][4];
            #pragma unroll
            for (int mt = 0; mt < 4; mt++){
                int rb = mt*16;
                splt(CS[(rb+r)*140 + k0 + q],         ah[mt][0], al[mt][0]);
                splt(CS[(rb+r+8)*140 + k0 + q],       ah[mt][1], al[mt][1]);
                splt(CS[(rb+r)*140 + k0 + q + 4],     ah[mt][2], al[mt][2]);
                splt(CS[(rb+r+8)*140 + k0 + q + 4],   ah[mt][3], al[mt][3]);
            }
            #pragma unroll
            for (int nt = 0; nt < 4; nt++){
                int col = n0 + (np*4 + nt)*8 + r;
                int o = (k0 + q)*512 + col;
                unsigned bh[2] = {__float_as_uint(__ldg(g_wl1_h + o)),
                                  __float_as_uint(__ldg(g_wl1_h + o + 2048))};
                unsigned bl[2] = {__float_as_uint(__ldg(g_wl1_l + o)),
                                  __float_as_uint(__ldg(g_wl1_l + o + 2048))};
                #pragma unroll
                for (int mt = 0; mt < 4; mt++){
                    mma8(acc[mt][nt], ah[mt], bh);
                    mma8(acc[mt][nt], ah[mt], bl);
                    mma8(acc[mt][nt], al[mt], bh);
                }
            }
        }
        #pragma unroll
        for (int mt = 0; mt < 4; mt++){
            #pragma unroll
            for (int nt = 0; nt < 4; nt++){
                int node = base + mt*16 + r;
                int col = n0 + (np*4 + nt)*8 + q*2;
                float b0 = __ldg(bl1 + col), b1 = __ldg(bl1 + col + 1);
                float2 u0, u1;
                u0.x = leaky(acc[mt][nt][0] + b0); u0.y = leaky(acc[mt][nt][1] + b1);
                u1.x = leaky(acc[mt][nt][2] + b0); u1.y = leaky(acc[mt][nt][3] + b1);
                *(float2*)(g_d2 + (size_t)node*512 + col)     = u0;
                *(float2*)(g_d2 + (size_t)(node+8)*512 + col) = u1;
            }
        }
    }
}

// ---------------- 4b) lin2: [BN x 512] @ [512 x 256] + max-pool --------------
__global__ void k_lin2(const float* __restrict__ bl2){
    __shared__ float As[64*68];
    int t = threadIdx.x, lane = t & 31, w = t >> 5;
    int base = blockIdx.x*64;
    int g = base / NN;
    int r = lane >> 2, q = lane & 3;
    int n0 = w*32;

    float acc[4][4][4];
    #pragma unroll
    for (int mt = 0; mt < 4; mt++)
        #pragma unroll
        for (int nt = 0; nt < 4; nt++)
            #pragma unroll
            for (int i = 0; i < 4; i++) acc[mt][nt][i] = 0.f;

    for (int kc = 0; kc < 512; kc += 64){
        __syncthreads();
        for (int i = t; i < 1024; i += 256){
            int m = i >> 4, kq = (i & 15)*4;
            float4 v = *(const float4*)(g_d2 + (size_t)(base + m)*512 + kc + kq);
            *(float4*)&As[m*68 + kq] = v;
        }
        __syncthreads();
        #pragma unroll
        for (int ks = 0; ks < 64; ks += 8){
            unsigned ah[4][4], al[4][4];
            #pragma unroll
            for (int mt = 0; mt < 4; mt++){
                int rb = mt*16;
                splt(As[(rb+r)*68 + ks + q],         ah[mt][0], al[mt][0]);
                splt(As[(rb+r+8)*68 + ks + q],       ah[mt][1], al[mt][1]);
                splt(As[(rb+r)*68 + ks + q + 4],     ah[mt][2], al[mt][2]);
                splt(As[(rb+r+8)*68 + ks + q + 4],   ah[mt][3], al[mt][3]);
            }
            #pragma unroll
            for (int nt = 0; nt < 4; nt++){
                int col = n0 + nt*8 + r;
                int o = (kc + ks + q)*256 + col;
                unsigned bh[2] = {__float_as_uint(__ldg(g_wl2_h + o)),
                                  __float_as_uint(__ldg(g_wl2_h + o + 1024))};
                unsigned bl[2] = {__float_as_uint(__ldg(g_wl2_l + o)),
                                  __float_as_uint(__ldg(g_wl2_l + o + 1024))};
                #pragma unroll
                for (int mt = 0; mt < 4; mt++){
                    mma8(acc[mt][nt], ah[mt], bh);
                    mma8(acc[mt][nt], ah[mt], bl);
                    mma8(acc[mt][nt], al[mt], bh);
                }
            }
        }
    }

    // per-graph max over this block's 64 nodes, then atomic into g_pool
    #pragma unroll
    for (int nt = 0; nt < 4; nt++){
        float m0 = -3.4e38f, m1 = -3.4e38f;
        #pragma unroll
        for (int mt = 0; mt < 4; mt++){
            m0 = fmaxf(m0, fmaxf(acc[mt][nt][0], acc[mt][nt][2]));
            m1 = fmaxf(m1, fmaxf(acc[mt][nt][1], acc[mt][nt][3]));
        }
        #pragma unroll
        for (int off = 4; off < 32; off <<= 1){
            m0 = fmaxf(m0, __shfl_xor_sync(0xffffffffu, m0, off));
            m1 = fmaxf(m1, __shfl_xor_sync(0xffffffffu, m1, off));
        }
        if (lane < 4){
            int col = n0 + nt*8 + lane*2;
            atomicMaxFloat(&g_pool[g*256 + col],     m0 + __ldg(bl2 + col));
            atomicMaxFloat(&g_pool[g*256 + col + 1], m1 + __ldg(bl2 + col + 1));
        }
    }
}

// ---------------- 5) head: leaky -> 256x128 -> leaky -> 128x3 ----------------
__global__ void k_head(const float* __restrict__ wm1, const float* __restrict__ bm1,
                       const float* __restrict__ wm2, const float* __restrict__ bm2,
                       float* __restrict__ out){
    __shared__ float gs[256];
    __shared__ float ms[128];
    int b = blockIdx.x, t = threadIdx.x;
    for (int c = t; c < 256; c += 128) gs[c] = leaky(g_pool[b*256 + c]);
    __syncthreads();
    float acc = bm1[t];
    #pragma unroll 8
    for (int d = 0; d < 256; d++) acc += gs[d]*wm1[d*128 + t];
    ms[t] = leaky(acc);
    __syncthreads();
    if (t < 3){
        float o = bm2[t];
        #pragma unroll 8
        for (int d = 0; d < 128; d++) o += ms[d]*wm2[d*3 + t];
        out[b*3 + t] = o;
    }
}

// -----------------------------------------------------------------------------
extern "C" void kernel_launch(void* const* d_in, const int* in_sizes, int n_in,
                              void* d_out, int out_size){
    const float* x   = (const float*)d_in[0];
    const float* pos = (const float*)d_in[1];
    const float* tq  = (const float*)d_in[2];
    const float* w1a = (const float*)d_in[4];
    const float* b1a = (const float*)d_in[5];
    const float* w1b = (const float*)d_in[6];
    const float* b1b = (const float*)d_in[7];
    const float* w2a = (const float*)d_in[8];
    const float* b2a = (const float*)d_in[9];
    const float* w2b = (const float*)d_in[10];
    const float* b2b = (const float*)d_in[11];
    const float* wl1 = (const float*)d_in[12];
    const float* bl1 = (const float*)d_in[13];
    const float* wl2 = (const float*)d_in[14];
    const float* bl2 = (const float*)d_in[15];
    const float* wm1 = (const float*)d_in[16];
    const float* bm1 = (const float*)d_in[17];
    const float* wm2 = (const float*)d_in[18];
    const float* bm2 = (const float*)d_in[19];
    float* out = (float*)d_out;

    k_prep<<<832, 256>>>(w1b, w2b, wl1, wl2);
    k_build<<<BN/256, 256>>>(x, pos, tq);
    k_initpool<<<(BATCH*256)/256, 256>>>();

    // conv1
    k_knn5<<<BATCH*(NN/8), 256>>>();
    k_convA1<<<(BN*64)/256, 256>>>(w1a, b1a);
    k_edge2t<64><<<BN/4, 128>>>(b1b);

    // conv2
    k_sq<<<BN/8, 256>>>();
    {
        dim3 grid(4, 4, BATCH);
        k_d2<<<grid, 256>>>();
    }
    k_select<<<BN/8, 256>>>();
    k_convA2<<<BN/16, 256>>>(w2a, b2a);
    k_edge2t<128><<<BN/4, 128>>>(b2b);

    // lin1 -> g_d2 (HS), lin2 + fused pool, head
    k_lin1<<<BN/64, 256>>>(bl1);
    k_lin2<<<BN/64, 256>>>(bl2);
    k_head<<<BATCH, 128>>>(wm1, bm1, wm2, bm2, out);
}